// round 10
// baseline (speedup 1.0000x reference)
#include <cuda_runtime.h>
#include <cuda_fp16.h>
#include <cstdint>
#include <cstddef>

// ---------------------------------------------------------------------------
// LoRALinear: fold NF4-dequant + LoRA into W' (fp16 RN); GEMM reads fp32 X
// DIRECTLY (cp.async fp32 A tiles, in-loop __floats2half2_rn pack), fp16 B via
// ldmatrix, fp16 m16n8k16 MMA with fp32 accum.
// R10 = R9 with the cp.async alignment bug fixed (LDS_WA 34 -> 36) and
// STAGES=3 to keep 2 CTAs/SM smem headroom.
// ---------------------------------------------------------------------------

#define IN_DIM   4096
#define OUT_DIM  4096
#define RANK_    16

__constant__ float c_nf4[16] = {
    -1.0f, -0.6961928009986877f, -0.5250730514526367f, -0.39491748809814453f,
    -0.28444138169288635f, -0.18477343022823334f, -0.09105003625154495f, 0.0f,
    0.07958029955625534f, 0.16093020141124725f, 0.24611230194568634f,
    0.33791524171829224f, 0.44070982933044434f, 0.5626170039176941f,
    0.7229568362236023f, 1.0f };

__device__ __half g_w[(size_t)OUT_DIM * IN_DIM];   // folded weight, fp16

// ---------------------------------------------------------------------------
// Kernel 1: W'[o,i] = nf4[wq]*scale + 2*(B@A)[o,i]  -> fp16 (RN)
// ---------------------------------------------------------------------------
__global__ void dequant_fold_kernel(const int* __restrict__ wq,
                                    const float* __restrict__ scales,
                                    const float* __restrict__ la,
                                    const float* __restrict__ lb,
                                    __half* __restrict__ W) {
    __shared__ float cb[16];
    if (threadIdx.x < 16) cb[threadIdx.x] = c_nf4[threadIdx.x];
    __syncthreads();

    int idx = blockIdx.x * blockDim.x + threadIdx.x;
    const int n4 = OUT_DIM * (IN_DIM / 4);
    if (idx >= n4) return;
    int o  = idx >> 10;
    int i4 = idx & 1023;

    int4 c = reinterpret_cast<const int4*>(wq)[idx];
    float s = scales[o * (IN_DIM / 64) + (i4 >> 4)];

    float lx = 0.f, ly = 0.f, lz = 0.f, lw = 0.f;
    #pragma unroll
    for (int r = 0; r < RANK_; r++) {
        float bb = __ldg(&lb[o * RANK_ + r]);
        float4 av = reinterpret_cast<const float4*>(la)[r * (IN_DIM / 4) + i4];
        lx = fmaf(bb, av.x, lx); ly = fmaf(bb, av.y, ly);
        lz = fmaf(bb, av.z, lz); lw = fmaf(bb, av.w, lw);
    }

    __half2 h0 = __floats2half2_rn(fmaf(cb[c.x], s, 2.0f * lx),
                                   fmaf(cb[c.y], s, 2.0f * ly));
    __half2 h1 = __floats2half2_rn(fmaf(cb[c.z], s, 2.0f * lz),
                                   fmaf(cb[c.w], s, 2.0f * lw));
    uint2 u = make_uint2(*reinterpret_cast<uint32_t*>(&h0),
                         *reinterpret_cast<uint32_t*>(&h1));
    reinterpret_cast<uint2*>(W)[idx] = u;
}

// ---------------------------------------------------------------------------
// Kernel 2: GEMM  C[M,N] = fp16(A_f32)[M,K] @ B[N,K]^T, fp32 accum.
// CTA 128x128x32, warp tile 64x32, 3-stage cp.async, 2 CTAs/SM.
// A staged as fp32 (LDS_WA=36 floats/row -> 144B rows, 16B-aligned).
// ---------------------------------------------------------------------------
#define BM 128
#define BN 128
#define BK 32
#define LDS_WA 36              // floats per A smem row (16B-aligned rows!)
#define LDS_H  40              // halves per B smem row
#define STAGES 3
#define A_ST  (BM * LDS_WA)    // floats per A stage = 4608
#define B_ST  (BN * LDS_H)     // halves per B stage = 5120

__device__ __forceinline__ unsigned smem_u32(const void* p) {
    return (unsigned)__cvta_generic_to_shared(p);
}

__global__ void __launch_bounds__(256, 2)
gemm_fp16_kernel(const float* __restrict__ A, const __half* __restrict__ B,
                 float* __restrict__ C, int M, int N, int K) {
    extern __shared__ char smraw[];
    float*  As = reinterpret_cast<float*>(smraw);
    __half* Bs = reinterpret_cast<__half*>(smraw + STAGES * A_ST * 4);

    const int tid  = threadIdx.x;
    const int lane = tid & 31;
    const int w    = tid >> 5;
    const int wm   = (w & 1) * 64;          // warp tile 64(M) x 32(N)
    const int wn   = (w >> 1) * 32;
    const int g    = lane >> 2;
    const int tg   = lane & 3;

    // 64 consecutive CTAs share one N-tile (B stays L2-resident per wave)
    const int mtile = blockIdx.x & 63;
    const int ntile = blockIdx.x >> 6;

    const int b_row_off = ((lane >> 4) & 1) * 8 + (lane & 7);
    const int b_khalf   = (lane >> 3) & 1;

    float acc[4][4][4];
    #pragma unroll
    for (int a = 0; a < 4; a++)
        #pragma unroll
        for (int b = 0; b < 4; b++)
            #pragma unroll
            for (int c = 0; c < 4; c++) acc[a][b][c] = 0.f;

    const int KT = K / BK;   // 128

    const float*  Abase = A + (size_t)(mtile * BM) * K;
    const __half* Bbase = B + (size_t)(ntile * BN) * K;

    auto load_stage = [&](int buf, int kt) {
        unsigned abase = smem_u32(As + (size_t)buf * A_ST);
        unsigned bbase = smem_u32(Bs + (size_t)buf * B_ST);
        // A: 128 rows x 8 chunks of 16B (fp32), 4 chunks/thread
        #pragma unroll
        for (int p = 0; p < 4; p++) {
            int cid = p * 256 + tid;
            int r = cid >> 3, c = cid & 7;
            unsigned dst = abase + (unsigned)((r * LDS_WA + c * 4) * 4);  // 16B-aligned
            const float* src = Abase + (size_t)r * K + kt * BK + c * 4;
            asm volatile("cp.async.cg.shared.global [%0], [%1], 16;\n"
                         :: "r"(dst), "l"(src));
        }
        // B: 128 rows x 4 chunks of 16B (fp16), 2 chunks/thread
        #pragma unroll
        for (int p = 0; p < 2; p++) {
            int cid = p * 256 + tid;
            int r = cid >> 2, c = cid & 3;
            unsigned dst = bbase + (unsigned)((r * LDS_H + c * 8) * 2);
            const __half* src = Bbase + (size_t)r * K + kt * BK + c * 8;
            asm volatile("cp.async.cg.shared.global [%0], [%1], 16;\n"
                         :: "r"(dst), "l"(src));
        }
    };

    load_stage(0, 0);
    asm volatile("cp.async.commit_group;\n");
    load_stage(1, 1);
    asm volatile("cp.async.commit_group;\n");

    int buf = 0;
    for (int kt = 0; kt < KT; kt++) {
        asm volatile("cp.async.wait_group 1;\n");
        __syncthreads();

        if (kt + 2 < KT) {
            int nbuf = buf + 2; if (nbuf >= STAGES) nbuf -= STAGES;
            load_stage(nbuf, kt + 2);
        }
        asm volatile("cp.async.commit_group;\n");

        const float* abuf = As + (size_t)buf * A_ST;
        unsigned bbuf = smem_u32(Bs + (size_t)buf * B_ST);

        #pragma unroll
        for (int ks = 0; ks < 2; ks++) {
            // B fragments via ldmatrix
            uint32_t bf[2][4];
            #pragma unroll
            for (int np = 0; np < 2; np++) {
                unsigned addr = bbuf + (unsigned)(((wn + np * 16 + b_row_off) * LDS_H
                                                  + ks * 16 + b_khalf * 8) * 2);
                asm volatile("ldmatrix.sync.aligned.m8n8.x4.shared.b16 "
                             "{%0,%1,%2,%3}, [%4];"
                             : "=r"(bf[np][0]), "=r"(bf[np][1]),
                               "=r"(bf[np][2]), "=r"(bf[np][3]) : "r"(addr));
            }
            // A fragments: float2 loads from fp32 smem + pack to fp16
            // m16n8k16 A layout: rows g / g+8, k = 2*tg + {0,1} (+8 for hi half)
            uint32_t af[4][4];
            #pragma unroll
            for (int mi = 0; mi < 4; mi++) {
                const float* p0 = abuf + (wm + mi * 16 + g) * LDS_WA
                                       + ks * 16 + 2 * tg;
                float2 f0 = *reinterpret_cast<const float2*>(p0);
                float2 f1 = *reinterpret_cast<const float2*>(p0 + 8 * LDS_WA);
                float2 f2 = *reinterpret_cast<const float2*>(p0 + 8);
                float2 f3 = *reinterpret_cast<const float2*>(p0 + 8 * LDS_WA + 8);
                __half2 h0 = __floats2half2_rn(f0.x, f0.y);
                __half2 h1 = __floats2half2_rn(f1.x, f1.y);
                __half2 h2 = __floats2half2_rn(f2.x, f2.y);
                __half2 h3 = __floats2half2_rn(f3.x, f3.y);
                af[mi][0] = *reinterpret_cast<uint32_t*>(&h0);
                af[mi][1] = *reinterpret_cast<uint32_t*>(&h1);
                af[mi][2] = *reinterpret_cast<uint32_t*>(&h2);
                af[mi][3] = *reinterpret_cast<uint32_t*>(&h3);
            }
            #pragma unroll
            for (int mi = 0; mi < 4; mi++)
                #pragma unroll
                for (int np = 0; np < 2; np++) {
                    asm volatile(
                        "mma.sync.aligned.m16n8k16.row.col.f32.f16.f16.f32 "
                        "{%0,%1,%2,%3}, {%4,%5,%6,%7}, {%8,%9}, {%0,%1,%2,%3};\n"
                        : "+f"(acc[mi][2*np][0]), "+f"(acc[mi][2*np][1]),
                          "+f"(acc[mi][2*np][2]), "+f"(acc[mi][2*np][3])
                        : "r"(af[mi][0]), "r"(af[mi][1]), "r"(af[mi][2]), "r"(af[mi][3]),
                          "r"(bf[np][0]), "r"(bf[np][1]));
                    asm volatile(
                        "mma.sync.aligned.m16n8k16.row.col.f32.f16.f16.f32 "
                        "{%0,%1,%2,%3}, {%4,%5,%6,%7}, {%8,%9}, {%0,%1,%2,%3};\n"
                        : "+f"(acc[mi][2*np+1][0]), "+f"(acc[mi][2*np+1][1]),
                          "+f"(acc[mi][2*np+1][2]), "+f"(acc[mi][2*np+1][3])
                        : "r"(af[mi][0]), "r"(af[mi][1]), "r"(af[mi][2]), "r"(af[mi][3]),
                          "r"(bf[np][2]), "r"(bf[np][3]));
                }
        }
        if (++buf == STAGES) buf = 0;
    }

    // epilogue
    #pragma unroll
    for (int mi = 0; mi < 4; mi++) {
        int row0 = mtile * BM + wm + mi * 16 + g;
        #pragma unroll
        for (int ni = 0; ni < 4; ni++) {
            int col = ntile * BN + wn + ni * 8 + tg * 2;
            float2 v0 = make_float2(acc[mi][ni][0], acc[mi][ni][1]);
            float2 v1 = make_float2(acc[mi][ni][2], acc[mi][ni][3]);
            *reinterpret_cast<float2*>(&C[(size_t)row0 * N + col])       = v0;
            *reinterpret_cast<float2*>(&C[(size_t)(row0 + 8) * N + col]) = v1;
        }
    }
}

// ---------------------------------------------------------------------------
// Launcher
// ---------------------------------------------------------------------------
extern "C" void kernel_launch(void* const* d_in, const int* in_sizes, int n_in,
                              void* d_out, int out_size) {
    const float* x      = (const float*)d_in[0];
    const int*   wq     = (const int*)  d_in[1];
    const float* scales = (const float*)d_in[2];
    const float* la     = (const float*)d_in[3];
    const float* lb     = (const float*)d_in[4];
    float* out = (float*)d_out;

    int M = in_sizes[0] / IN_DIM;    // 8192

    __half* gw = nullptr;
    cudaGetSymbolAddress((void**)&gw, g_w);

    int n4w = OUT_DIM * (IN_DIM / 4);
    dequant_fold_kernel<<<(n4w + 255) / 256, 256>>>(wq, scales, la, lb, gw);

    const int smem_bytes = STAGES * (A_ST * 4 + B_ST * 2);   // 86016
    cudaFuncSetAttribute(gemm_fp16_kernel,
                         cudaFuncAttributeMaxDynamicSharedMemorySize, smem_bytes);
    int grid = (M / BM) * (OUT_DIM / BN);   // 64 * 32 = 2048
    gemm_fp16_kernel<<<grid, 256, smem_bytes>>>(x, gw, out, M, OUT_DIM, IN_DIM);
}

// round 11
// speedup vs baseline: 1.5049x; 1.5049x over previous
#include <cuda_runtime.h>
#include <cuda_fp16.h>
#include <cstdint>
#include <cstddef>

// ---------------------------------------------------------------------------
// LoRALinear: fold NF4-dequant + LoRA into W' (fp16 RN). GEMM reads fp32 X
// directly: LDG.128 fp32 -> cvt in regs -> STS.64 fp16 into the SAME smem
// layout as the champion; ldmatrix fragment path unchanged (R10's mistake was
// converting on the fragment-READ side). B via cp.async. CTA 128x256,
// warp tile 64x64, 1 CTA/SM, 3-stage. round_x kernel deleted.
// ---------------------------------------------------------------------------

#define IN_DIM   4096
#define OUT_DIM  4096
#define RANK_    16

__constant__ float c_nf4[16] = {
    -1.0f, -0.6961928009986877f, -0.5250730514526367f, -0.39491748809814453f,
    -0.28444138169288635f, -0.18477343022823334f, -0.09105003625154495f, 0.0f,
    0.07958029955625534f, 0.16093020141124725f, 0.24611230194568634f,
    0.33791524171829224f, 0.44070982933044434f, 0.5626170039176941f,
    0.7229568362236023f, 1.0f };

__device__ __half g_w[(size_t)OUT_DIM * IN_DIM];   // folded weight, fp16

// ---------------------------------------------------------------------------
// Kernel 1: W'[o,i] = nf4[wq]*scale + 2*(B@A)[o,i]  -> fp16 (RN)
// ---------------------------------------------------------------------------
__global__ void dequant_fold_kernel(const int* __restrict__ wq,
                                    const float* __restrict__ scales,
                                    const float* __restrict__ la,
                                    const float* __restrict__ lb,
                                    __half* __restrict__ W) {
    __shared__ float cb[16];
    if (threadIdx.x < 16) cb[threadIdx.x] = c_nf4[threadIdx.x];
    __syncthreads();

    int idx = blockIdx.x * blockDim.x + threadIdx.x;
    const int n4 = OUT_DIM * (IN_DIM / 4);
    if (idx >= n4) return;
    int o  = idx >> 10;
    int i4 = idx & 1023;

    int4 c = reinterpret_cast<const int4*>(wq)[idx];
    float s = scales[o * (IN_DIM / 64) + (i4 >> 4)];

    float lx = 0.f, ly = 0.f, lz = 0.f, lw = 0.f;
    #pragma unroll
    for (int r = 0; r < RANK_; r++) {
        float bb = __ldg(&lb[o * RANK_ + r]);
        float4 av = reinterpret_cast<const float4*>(la)[r * (IN_DIM / 4) + i4];
        lx = fmaf(bb, av.x, lx); ly = fmaf(bb, av.y, ly);
        lz = fmaf(bb, av.z, lz); lw = fmaf(bb, av.w, lw);
    }

    __half2 h0 = __floats2half2_rn(fmaf(cb[c.x], s, 2.0f * lx),
                                   fmaf(cb[c.y], s, 2.0f * ly));
    __half2 h1 = __floats2half2_rn(fmaf(cb[c.z], s, 2.0f * lz),
                                   fmaf(cb[c.w], s, 2.0f * lw));
    uint2 u = make_uint2(*reinterpret_cast<uint32_t*>(&h0),
                         *reinterpret_cast<uint32_t*>(&h1));
    reinterpret_cast<uint2*>(W)[idx] = u;
}

// ---------------------------------------------------------------------------
// Kernel 2: GEMM  C[M,N] = fp16(A_f32)[M,K] @ B[N,K]^T, fp32 accum.
// CTA 128x256x32, 8 warps 2(M)x4(N), warp tile 64x64, 3 stages, 1 CTA/SM.
// A: LDG fp32 -> cvt -> STS fp16 (store-side conversion). B: cp.async fp16.
// ---------------------------------------------------------------------------
#define BM 128
#define BN 256
#define BK 32
#define LDS_H  40              // halves per smem row (conflict-free pad)
#define STAGES 3
#define A_ST  (BM * LDS_H)     // halves per A stage  = 5120
#define B_ST  (BN * LDS_H)     // halves per B stage  = 10240

__device__ __forceinline__ unsigned smem_u32(const void* p) {
    return (unsigned)__cvta_generic_to_shared(p);
}

__global__ void __launch_bounds__(256, 1)
gemm_fp16_kernel(const float* __restrict__ A, const __half* __restrict__ B,
                 float* __restrict__ C, int M, int N, int K) {
    extern __shared__ __half sm[];
    __half* As = sm;                        // STAGES * A_ST
    __half* Bs = sm + STAGES * A_ST;        // STAGES * B_ST

    const int tid  = threadIdx.x;
    const int lane = tid & 31;
    const int w    = tid >> 5;
    const int wm   = (w & 1) * 64;          // warp tile 64(M) x 64(N)
    const int wn   = (w >> 1) * 64;
    const int g    = lane >> 2;
    const int tg   = lane & 3;

    // 64 consecutive CTAs share one N-tile; per-kt A/B slices stay L2-resident
    const int mtile = blockIdx.x & 63;
    const int ntile = blockIdx.x >> 6;      // 16 N-tiles

    const int a_row_off = (lane & 7) + ((lane >> 3) & 1) * 8;
    const int a_khalf   = (lane >> 4);
    const int b_row_off = ((lane >> 4) & 1) * 8 + (lane & 7);
    const int b_khalf   = (lane >> 3) & 1;

    float acc[4][8][4];
    #pragma unroll
    for (int a = 0; a < 4; a++)
        #pragma unroll
        for (int b = 0; b < 8; b++)
            #pragma unroll
            for (int c = 0; c < 4; c++) acc[a][b][c] = 0.f;

    const int KT = K / BK;   // 128

    const float*  Abase = A + (size_t)(mtile * BM) * K;
    const __half* Bbase = B + (size_t)(ntile * BN) * K;

    // ---- A path: LDG fp32 into regs, convert, STS fp16 ----
    // 128 rows x 8 chunks of 16B(fp32) = 1024 chunks; 4 per thread.
    float4 apre[4];
    auto ldgA = [&](int kt) {
        #pragma unroll
        for (int p = 0; p < 4; p++) {
            int cid = p * 256 + tid;
            int r = cid >> 3, c = cid & 7;
            apre[p] = *reinterpret_cast<const float4*>(
                Abase + (size_t)r * K + kt * BK + c * 4);
        }
    };
    auto stsA = [&](int buf) {
        #pragma unroll
        for (int p = 0; p < 4; p++) {
            int cid = p * 256 + tid;
            int r = cid >> 3, c = cid & 7;
            __half2 h0 = __floats2half2_rn(apre[p].x, apre[p].y);
            __half2 h1 = __floats2half2_rn(apre[p].z, apre[p].w);
            uint2 u = make_uint2(*reinterpret_cast<uint32_t*>(&h0),
                                 *reinterpret_cast<uint32_t*>(&h1));
            *reinterpret_cast<uint2*>(
                &As[(size_t)buf * A_ST + r * LDS_H + c * 4]) = u;
        }
    };

    // ---- B path: cp.async fp16 (256 rows x 4 chunks of 16B; 4/thread) ----
    auto cpB = [&](int buf, int kt) {
        unsigned bbase = smem_u32(Bs + (size_t)buf * B_ST);
        #pragma unroll
        for (int p = 0; p < 4; p++) {
            int cid = p * 256 + tid;
            int r = cid >> 2, c = cid & 3;
            unsigned dst = bbase + (unsigned)((r * LDS_H + c * 8) * 2);
            const __half* src = Bbase + (size_t)r * K + kt * BK + c * 8;
            asm volatile("cp.async.cg.shared.global [%0], [%1], 16;\n"
                         :: "r"(dst), "l"(src));
        }
    };

    // prologue: A0 -> smem stage0; A1 held in regs; B0,B1 in flight
    ldgA(0);
    stsA(0);
    ldgA(1);
    cpB(0, 0);
    asm volatile("cp.async.commit_group;\n");
    cpB(1, 1);
    asm volatile("cp.async.commit_group;\n");

    int buf = 0;
    for (int kt = 0; kt < KT; kt++) {
        asm volatile("cp.async.wait_group 1;\n");   // B(kt) resident
        __syncthreads();                            // A(kt) STS visible

        // stage kt+1: store prefetched A; prefetch kt+2
        int nb1 = buf + 1; if (nb1 >= STAGES) nb1 -= STAGES;
        int nb2 = buf + 2; if (nb2 >= STAGES) nb2 -= STAGES;
        if (kt + 1 < KT) stsA(nb1);
        if (kt + 2 < KT) { ldgA(kt + 2); cpB(nb2, kt + 2); }
        asm volatile("cp.async.commit_group;\n");

        unsigned abuf = smem_u32(As + (size_t)buf * A_ST);
        unsigned bbuf = smem_u32(Bs + (size_t)buf * B_ST);

        #pragma unroll
        for (int ks = 0; ks < 2; ks++) {
            uint32_t af[4][4], bf[4][4];
            #pragma unroll
            for (int mi = 0; mi < 4; mi++) {
                unsigned addr = abuf + (unsigned)(((wm + mi * 16 + a_row_off) * LDS_H
                                                  + ks * 16 + a_khalf * 8) * 2);
                asm volatile("ldmatrix.sync.aligned.m8n8.x4.shared.b16 "
                             "{%0,%1,%2,%3}, [%4];"
                             : "=r"(af[mi][0]), "=r"(af[mi][1]),
                               "=r"(af[mi][2]), "=r"(af[mi][3]) : "r"(addr));
            }
            #pragma unroll
            for (int np = 0; np < 4; np++) {
                unsigned addr = bbuf + (unsigned)(((wn + np * 16 + b_row_off) * LDS_H
                                                  + ks * 16 + b_khalf * 8) * 2);
                asm volatile("ldmatrix.sync.aligned.m8n8.x4.shared.b16 "
                             "{%0,%1,%2,%3}, [%4];"
                             : "=r"(bf[np][0]), "=r"(bf[np][1]),
                               "=r"(bf[np][2]), "=r"(bf[np][3]) : "r"(addr));
            }
            #pragma unroll
            for (int mi = 0; mi < 4; mi++)
                #pragma unroll
                for (int np = 0; np < 4; np++) {
                    asm volatile(
                        "mma.sync.aligned.m16n8k16.row.col.f32.f16.f16.f32 "
                        "{%0,%1,%2,%3}, {%4,%5,%6,%7}, {%8,%9}, {%0,%1,%2,%3};\n"
                        : "+f"(acc[mi][2*np][0]), "+f"(acc[mi][2*np][1]),
                          "+f"(acc[mi][2*np][2]), "+f"(acc[mi][2*np][3])
                        : "r"(af[mi][0]), "r"(af[mi][1]), "r"(af[mi][2]), "r"(af[mi][3]),
                          "r"(bf[np][0]), "r"(bf[np][1]));
                    asm volatile(
                        "mma.sync.aligned.m16n8k16.row.col.f32.f16.f16.f32 "
                        "{%0,%1,%2,%3}, {%4,%5,%6,%7}, {%8,%9}, {%0,%1,%2,%3};\n"
                        : "+f"(acc[mi][2*np+1][0]), "+f"(acc[mi][2*np+1][1]),
                          "+f"(acc[mi][2*np+1][2]), "+f"(acc[mi][2*np+1][3])
                        : "r"(af[mi][0]), "r"(af[mi][1]), "r"(af[mi][2]), "r"(af[mi][3]),
                          "r"(bf[np][2]), "r"(bf[np][3]));
                }
        }
        if (++buf == STAGES) buf = 0;
    }

    // epilogue
    #pragma unroll
    for (int mi = 0; mi < 4; mi++) {
        int row0 = mtile * BM + wm + mi * 16 + g;
        #pragma unroll
        for (int ni = 0; ni < 8; ni++) {
            int col = ntile * BN + wn + ni * 8 + tg * 2;
            float2 v0 = make_float2(acc[mi][ni][0], acc[mi][ni][1]);
            float2 v1 = make_float2(acc[mi][ni][2], acc[mi][ni][3]);
            *reinterpret_cast<float2*>(&C[(size_t)row0 * N + col])       = v0;
            *reinterpret_cast<float2*>(&C[(size_t)(row0 + 8) * N + col]) = v1;
        }
    }
}

// ---------------------------------------------------------------------------
// Launcher
// ---------------------------------------------------------------------------
extern "C" void kernel_launch(void* const* d_in, const int* in_sizes, int n_in,
                              void* d_out, int out_size) {
    const float* x      = (const float*)d_in[0];
    const int*   wq     = (const int*)  d_in[1];
    const float* scales = (const float*)d_in[2];
    const float* la     = (const float*)d_in[3];
    const float* lb     = (const float*)d_in[4];
    float* out = (float*)d_out;

    int M = in_sizes[0] / IN_DIM;    // 8192

    __half* gw = nullptr;
    cudaGetSymbolAddress((void**)&gw, g_w);

    int n4w = OUT_DIM * (IN_DIM / 4);
    dequant_fold_kernel<<<(n4w + 255) / 256, 256>>>(wq, scales, la, lb, gw);

    const int smem_bytes = STAGES * (A_ST + B_ST) * (int)sizeof(__half); // 92160
    cudaFuncSetAttribute(gemm_fp16_kernel,
                         cudaFuncAttributeMaxDynamicSharedMemorySize, smem_bytes);
    int grid = (M / BM) * (OUT_DIM / BN);   // 64 * 16 = 1024
    gemm_fp16_kernel<<<grid, 256, smem_bytes>>>(x, gw, out, M, OUT_DIM, IN_DIM);
}

// round 12
// speedup vs baseline: 1.6218x; 1.0777x over previous
#include <cuda_runtime.h>
#include <cuda_fp16.h>
#include <cstdint>
#include <cstddef>

// ---------------------------------------------------------------------------
// LoRALinear champion configuration:
//  - ONE prep kernel (branching): X->fp16 RN  AND  W' = NF4-dequant + LoRA fold
//  - fp16 m16n8k16 GEMM, fp32 accum, CTA 128x128x32, warp tile 64x32,
//    4-stage cp.async, 2 CTAs/SM (R5 mainloop: 97-98% of legacy-HMMA wall rate)
// ---------------------------------------------------------------------------

#define IN_DIM   4096
#define OUT_DIM  4096
#define RANK_    16
#define M_MAX    8192

__constant__ float c_nf4[16] = {
    -1.0f, -0.6961928009986877f, -0.5250730514526367f, -0.39491748809814453f,
    -0.28444138169288635f, -0.18477343022823334f, -0.09105003625154495f, 0.0f,
    0.07958029955625534f, 0.16093020141124725f, 0.24611230194568634f,
    0.33791524171829224f, 0.44070982933044434f, 0.5626170039176941f,
    0.7229568362236023f, 1.0f };

__device__ __half g_w[(size_t)OUT_DIM * IN_DIM];
__device__ __half g_x[(size_t)M_MAX * IN_DIM];

// ---------------------------------------------------------------------------
// Prep kernel: blocks [0, nblk_x) round X; blocks [nblk_x, ...) dequant+fold W'
// ---------------------------------------------------------------------------
__global__ void prep_kernel(const float* __restrict__ x, __half* __restrict__ xr,
                            int n8, int nblk_x,
                            const int* __restrict__ wq,
                            const float* __restrict__ scales,
                            const float* __restrict__ la,
                            const float* __restrict__ lb,
                            __half* __restrict__ W) {
    if (blockIdx.x < (unsigned)nblk_x) {
        // ---- X -> fp16 (RN), 8 elems/thread ----
        int i = blockIdx.x * blockDim.x + threadIdx.x;
        if (i >= n8) return;
        float4 v0 = reinterpret_cast<const float4*>(x)[2 * i];
        float4 v1 = reinterpret_cast<const float4*>(x)[2 * i + 1];
        __half2 h[4];
        h[0] = __floats2half2_rn(v0.x, v0.y);
        h[1] = __floats2half2_rn(v0.z, v0.w);
        h[2] = __floats2half2_rn(v1.x, v1.y);
        h[3] = __floats2half2_rn(v1.z, v1.w);
        reinterpret_cast<uint4*>(xr)[i] = *reinterpret_cast<uint4*>(h);
    } else {
        // ---- W'[o,i] = nf4[wq]*scale + 2*(B@A)[o,i] -> fp16 (RN) ----
        __shared__ float cb[16];
        if (threadIdx.x < 16) cb[threadIdx.x] = c_nf4[threadIdx.x];
        __syncthreads();

        int idx = (blockIdx.x - nblk_x) * blockDim.x + threadIdx.x;
        const int n4 = OUT_DIM * (IN_DIM / 4);
        if (idx >= n4) return;
        int o  = idx >> 10;
        int i4 = idx & 1023;

        int4 c = reinterpret_cast<const int4*>(wq)[idx];
        float s = scales[o * (IN_DIM / 64) + (i4 >> 4)];

        float lx = 0.f, ly = 0.f, lz = 0.f, lw = 0.f;
        #pragma unroll
        for (int r = 0; r < RANK_; r++) {
            float bb = __ldg(&lb[o * RANK_ + r]);
            float4 av = reinterpret_cast<const float4*>(la)[r * (IN_DIM / 4) + i4];
            lx = fmaf(bb, av.x, lx); ly = fmaf(bb, av.y, ly);
            lz = fmaf(bb, av.z, lz); lw = fmaf(bb, av.w, lw);
        }

        __half2 h0 = __floats2half2_rn(fmaf(cb[c.x], s, 2.0f * lx),
                                       fmaf(cb[c.y], s, 2.0f * ly));
        __half2 h1 = __floats2half2_rn(fmaf(cb[c.z], s, 2.0f * lz),
                                       fmaf(cb[c.w], s, 2.0f * lw));
        uint2 u = make_uint2(*reinterpret_cast<uint32_t*>(&h0),
                             *reinterpret_cast<uint32_t*>(&h1));
        reinterpret_cast<uint2*>(W)[idx] = u;
    }
}

// ---------------------------------------------------------------------------
// GEMM: fp16 m16n8k16, CTA 128x128x32, 8 warps 2(M)x4(N), warp tile 64x32.
// 4-stage cp.async, 2 CTAs/SM.  (R5 mainloop verbatim.)
// ---------------------------------------------------------------------------
#define BM 128
#define BN 128
#define BK 32
#define LDS_H  40
#define STAGES 4
#define A_ST  (BM * LDS_H)
#define B_ST  (BN * LDS_H)

__device__ __forceinline__ unsigned smem_u32(const void* p) {
    return (unsigned)__cvta_generic_to_shared(p);
}

__global__ void __launch_bounds__(256, 2)
gemm_fp16_kernel(const __half* __restrict__ A, const __half* __restrict__ B,
                 float* __restrict__ C, int M, int N, int K) {
    extern __shared__ __half sm[];
    __half* As = sm;
    __half* Bs = sm + STAGES * A_ST;

    const int tid  = threadIdx.x;
    const int lane = tid & 31;
    const int w    = tid >> 5;
    const int wm   = (w & 1) * 64;          // warp tile 64(M) x 32(N)
    const int wn   = (w >> 1) * 32;
    const int g    = lane >> 2;
    const int tg   = lane & 3;

    // 64 consecutive CTAs share one N-tile (B L2-resident per wave)
    const int mtile = blockIdx.x & 63;      // 64 M-tiles
    const int ntile = blockIdx.x >> 6;      // 32 N-tiles

    const int a_row_off = (lane & 7) + ((lane >> 3) & 1) * 8;
    const int a_khalf   = (lane >> 4);
    const int b_row_off = ((lane >> 4) & 1) * 8 + (lane & 7);
    const int b_khalf   = (lane >> 3) & 1;

    float acc[4][4][4];
    #pragma unroll
    for (int a = 0; a < 4; a++)
        #pragma unroll
        for (int b = 0; b < 4; b++)
            #pragma unroll
            for (int c = 0; c < 4; c++) acc[a][b][c] = 0.f;

    const int KT = K / BK;   // 128

    const __half* Abase = A + (size_t)(mtile * BM) * K;
    const __half* Bbase = B + (size_t)(ntile * BN) * K;

    auto load_stage = [&](int buf, int kt) {
        unsigned abase = smem_u32(As + (size_t)buf * A_ST);
        unsigned bbase = smem_u32(Bs + (size_t)buf * B_ST);
        #pragma unroll
        for (int p = 0; p < 2; p++) {       // A: 128 rows x 4 chunks
            int cid = p * 256 + tid;
            int r = cid >> 2, c = cid & 3;
            unsigned dst = abase + (unsigned)((r * LDS_H + c * 8) * 2);
            const __half* src = Abase + (size_t)r * K + kt * BK + c * 8;
            asm volatile("cp.async.cg.shared.global [%0], [%1], 16;\n"
                         :: "r"(dst), "l"(src));
        }
        #pragma unroll
        for (int p = 0; p < 2; p++) {       // B: 128 rows x 4 chunks
            int cid = p * 256 + tid;
            int r = cid >> 2, c = cid & 3;
            unsigned dst = bbase + (unsigned)((r * LDS_H + c * 8) * 2);
            const __half* src = Bbase + (size_t)r * K + kt * BK + c * 8;
            asm volatile("cp.async.cg.shared.global [%0], [%1], 16;\n"
                         :: "r"(dst), "l"(src));
        }
    };

    load_stage(0, 0);
    asm volatile("cp.async.commit_group;\n");
    load_stage(1, 1);
    asm volatile("cp.async.commit_group;\n");
    load_stage(2, 2);
    asm volatile("cp.async.commit_group;\n");

    int buf = 0;
    for (int kt = 0; kt < KT; kt++) {
        asm volatile("cp.async.wait_group 2;\n");
        __syncthreads();

        if (kt + 3 < KT) load_stage((buf + 3) & 3, kt + 3);
        asm volatile("cp.async.commit_group;\n");

        unsigned abuf = smem_u32(As + (size_t)buf * A_ST);
        unsigned bbuf = smem_u32(Bs + (size_t)buf * B_ST);

        #pragma unroll
        for (int ks = 0; ks < 2; ks++) {
            uint32_t af[4][4], bf[2][4];
            #pragma unroll
            for (int mi = 0; mi < 4; mi++) {
                unsigned addr = abuf + (unsigned)(((wm + mi * 16 + a_row_off) * LDS_H
                                                  + ks * 16 + a_khalf * 8) * 2);
                asm volatile("ldmatrix.sync.aligned.m8n8.x4.shared.b16 "
                             "{%0,%1,%2,%3}, [%4];"
                             : "=r"(af[mi][0]), "=r"(af[mi][1]),
                               "=r"(af[mi][2]), "=r"(af[mi][3]) : "r"(addr));
            }
            #pragma unroll
            for (int np = 0; np < 2; np++) {
                unsigned addr = bbuf + (unsigned)(((wn + np * 16 + b_row_off) * LDS_H
                                                  + ks * 16 + b_khalf * 8) * 2);
                asm volatile("ldmatrix.sync.aligned.m8n8.x4.shared.b16 "
                             "{%0,%1,%2,%3}, [%4];"
                             : "=r"(bf[np][0]), "=r"(bf[np][1]),
                               "=r"(bf[np][2]), "=r"(bf[np][3]) : "r"(addr));
            }
            #pragma unroll
            for (int mi = 0; mi < 4; mi++)
                #pragma unroll
                for (int np = 0; np < 2; np++) {
                    asm volatile(
                        "mma.sync.aligned.m16n8k16.row.col.f32.f16.f16.f32 "
                        "{%0,%1,%2,%3}, {%4,%5,%6,%7}, {%8,%9}, {%0,%1,%2,%3};\n"
                        : "+f"(acc[mi][2*np][0]), "+f"(acc[mi][2*np][1]),
                          "+f"(acc[mi][2*np][2]), "+f"(acc[mi][2*np][3])
                        : "r"(af[mi][0]), "r"(af[mi][1]), "r"(af[mi][2]), "r"(af[mi][3]),
                          "r"(bf[np][0]), "r"(bf[np][1]));
                    asm volatile(
                        "mma.sync.aligned.m16n8k16.row.col.f32.f16.f16.f32 "
                        "{%0,%1,%2,%3}, {%4,%5,%6,%7}, {%8,%9}, {%0,%1,%2,%3};\n"
                        : "+f"(acc[mi][2*np+1][0]), "+f"(acc[mi][2*np+1][1]),
                          "+f"(acc[mi][2*np+1][2]), "+f"(acc[mi][2*np+1][3])
                        : "r"(af[mi][0]), "r"(af[mi][1]), "r"(af[mi][2]), "r"(af[mi][3]),
                          "r"(bf[np][2]), "r"(bf[np][3]));
                }
        }
        buf = (buf + 1) & 3;
    }

    // epilogue
    #pragma unroll
    for (int mi = 0; mi < 4; mi++) {
        int row0 = mtile * BM + wm + mi * 16 + g;
        #pragma unroll
        for (int ni = 0; ni < 4; ni++) {
            int col = ntile * BN + wn + ni * 8 + tg * 2;
            float2 v0 = make_float2(acc[mi][ni][0], acc[mi][ni][1]);
            float2 v1 = make_float2(acc[mi][ni][2], acc[mi][ni][3]);
            *reinterpret_cast<float2*>(&C[(size_t)row0 * N + col])       = v0;
            *reinterpret_cast<float2*>(&C[(size_t)(row0 + 8) * N + col]) = v1;
        }
    }
}

// ---------------------------------------------------------------------------
// Launcher
// ---------------------------------------------------------------------------
extern "C" void kernel_launch(void* const* d_in, const int* in_sizes, int n_in,
                              void* d_out, int out_size) {
    const float* x      = (const float*)d_in[0];
    const int*   wq     = (const int*)  d_in[1];
    const float* scales = (const float*)d_in[2];
    const float* la     = (const float*)d_in[3];
    const float* lb     = (const float*)d_in[4];
    float* out = (float*)d_out;

    int M = in_sizes[0] / IN_DIM;    // 8192

    __half *gw = nullptr, *gx = nullptr;
    cudaGetSymbolAddress((void**)&gw, g_w);
    cudaGetSymbolAddress((void**)&gx, g_x);

    // ONE prep launch: X rounding + W' dequant/fold
    int n8x    = (M * IN_DIM) / 8;
    int nblk_x = (n8x + 255) / 256;                       // 16384
    int n4w    = OUT_DIM * (IN_DIM / 4);
    int nblk_w = (n4w + 255) / 256;                       // 16384
    prep_kernel<<<nblk_x + nblk_w, 256>>>(x, gx, n8x, nblk_x,
                                          wq, scales, la, lb, gw);

    const int smem_bytes = STAGES * (A_ST + B_ST) * (int)sizeof(__half); // 81920
    cudaFuncSetAttribute(gemm_fp16_kernel,
                         cudaFuncAttributeMaxDynamicSharedMemorySize, smem_bytes);
    int grid = (M / BM) * (OUT_DIM / BN);   // 2048
    gemm_fp16_kernel<<<grid, 256, smem_bytes>>>(gx, gw, out, M, OUT_DIM, IN_DIM);
}

// round 13
// speedup vs baseline: 1.8779x; 1.1579x over previous
#include <cuda_runtime.h>
#include <cuda_fp16.h>
#include <cstdint>
#include <cstddef>

// ---------------------------------------------------------------------------
// LoRALinear champion v2:
//  - ONE prep kernel (branch): X->fp16 RN AND W' = NF4-dequant + LoRA fold,
//    with programmatic-launch-completion trigger (PDL).
//  - fp16 m16n8k16 GEMM, fp32 accum, CTA 128x128xBK64, warp tile 64x32,
//    3-stage cp.async, 2 CTAs/SM, griddepcontrol.wait before first load.
// ---------------------------------------------------------------------------

#define IN_DIM   4096
#define OUT_DIM  4096
#define RANK_    16
#define M_MAX    8192

__constant__ float c_nf4[16] = {
    -1.0f, -0.6961928009986877f, -0.5250730514526367f, -0.39491748809814453f,
    -0.28444138169288635f, -0.18477343022823334f, -0.09105003625154495f, 0.0f,
    0.07958029955625534f, 0.16093020141124725f, 0.24611230194568634f,
    0.33791524171829224f, 0.44070982933044434f, 0.5626170039176941f,
    0.7229568362236023f, 1.0f };

__device__ __half g_w[(size_t)OUT_DIM * IN_DIM];
__device__ __half g_x[(size_t)M_MAX * IN_DIM];

// ---------------------------------------------------------------------------
// Prep kernel: blocks [0,nblk_x) round X; rest dequant+fold W'
// ---------------------------------------------------------------------------
__global__ void prep_kernel(const float* __restrict__ x, __half* __restrict__ xr,
                            int n8, int nblk_x,
                            const int* __restrict__ wq,
                            const float* __restrict__ scales,
                            const float* __restrict__ la,
                            const float* __restrict__ lb,
                            __half* __restrict__ W) {
    if (blockIdx.x < (unsigned)nblk_x) {
        int i = blockIdx.x * blockDim.x + threadIdx.x;
        if (i < n8) {
            float4 v0 = reinterpret_cast<const float4*>(x)[2 * i];
            float4 v1 = reinterpret_cast<const float4*>(x)[2 * i + 1];
            __half2 h[4];
            h[0] = __floats2half2_rn(v0.x, v0.y);
            h[1] = __floats2half2_rn(v0.z, v0.w);
            h[2] = __floats2half2_rn(v1.x, v1.y);
            h[3] = __floats2half2_rn(v1.z, v1.w);
            reinterpret_cast<uint4*>(xr)[i] = *reinterpret_cast<uint4*>(h);
        }
    } else {
        __shared__ float cb[16];
        if (threadIdx.x < 16) cb[threadIdx.x] = c_nf4[threadIdx.x];
        __syncthreads();

        int idx = (blockIdx.x - nblk_x) * blockDim.x + threadIdx.x;
        const int n4 = OUT_DIM * (IN_DIM / 4);
        if (idx < n4) {
            int o  = idx >> 10;
            int i4 = idx & 1023;

            int4 c = reinterpret_cast<const int4*>(wq)[idx];
            float s = scales[o * (IN_DIM / 64) + (i4 >> 4)];

            float lx = 0.f, ly = 0.f, lz = 0.f, lw = 0.f;
            #pragma unroll
            for (int r = 0; r < RANK_; r++) {
                float bb = __ldg(&lb[o * RANK_ + r]);
                float4 av = reinterpret_cast<const float4*>(la)[r * (IN_DIM / 4) + i4];
                lx = fmaf(bb, av.x, lx); ly = fmaf(bb, av.y, ly);
                lz = fmaf(bb, av.z, lz); lw = fmaf(bb, av.w, lw);
            }

            __half2 h0 = __floats2half2_rn(fmaf(cb[c.x], s, 2.0f * lx),
                                           fmaf(cb[c.y], s, 2.0f * ly));
            __half2 h1 = __floats2half2_rn(fmaf(cb[c.z], s, 2.0f * lz),
                                           fmaf(cb[c.w], s, 2.0f * lw));
            uint2 u = make_uint2(*reinterpret_cast<uint32_t*>(&h0),
                                 *reinterpret_cast<uint32_t*>(&h1));
            reinterpret_cast<uint2*>(W)[idx] = u;
        }
    }
#if __CUDA_ARCH__ >= 900
    cudaTriggerProgrammaticLaunchCompletion();
#endif
}

// ---------------------------------------------------------------------------
// GEMM: fp16 m16n8k16, CTA 128x128x64, 8 warps 2(M)x4(N), warp tile 64x32.
// 3-stage cp.async (2 in flight), 2 CTAs/SM.
// ---------------------------------------------------------------------------
#define BM 128
#define BN 128
#define BK 64
#define LDS_H  72              // halves per smem row (144B: aligned + conflict-free)
#define STAGES 3
#define A_ST  (BM * LDS_H)     // 9216 halves
#define B_ST  (BN * LDS_H)     // 9216 halves

__device__ __forceinline__ unsigned smem_u32(const void* p) {
    return (unsigned)__cvta_generic_to_shared(p);
}

__global__ void __launch_bounds__(256, 2)
gemm_fp16_kernel(const __half* __restrict__ A, const __half* __restrict__ B,
                 float* __restrict__ C, int M, int N, int K) {
    extern __shared__ __half sm[];
    __half* As = sm;
    __half* Bs = sm + STAGES * A_ST;

    const int tid  = threadIdx.x;
    const int lane = tid & 31;
    const int w    = tid >> 5;
    const int wm   = (w & 1) * 64;          // warp tile 64(M) x 32(N)
    const int wn   = (w >> 1) * 32;
    const int g    = lane >> 2;
    const int tg   = lane & 3;

    // 64 consecutive CTAs share one N-tile (R12 mapping: fastest measured)
    const int mtile = blockIdx.x & 63;
    const int ntile = blockIdx.x >> 6;

    const int a_row_off = (lane & 7) + ((lane >> 3) & 1) * 8;
    const int a_khalf   = (lane >> 4);
    const int b_row_off = ((lane >> 4) & 1) * 8 + (lane & 7);
    const int b_khalf   = (lane >> 3) & 1;

    float acc[4][4][4];
    #pragma unroll
    for (int a = 0; a < 4; a++)
        #pragma unroll
        for (int b = 0; b < 4; b++)
            #pragma unroll
            for (int c = 0; c < 4; c++) acc[a][b][c] = 0.f;

    const int KT = K / BK;   // 64

    const __half* Abase = A + (size_t)(mtile * BM) * K;
    const __half* Bbase = B + (size_t)(ntile * BN) * K;

#if __CUDA_ARCH__ >= 900
    cudaGridDependencySynchronize();   // PDL: wait for prep's writes
#endif

    auto load_stage = [&](int buf, int kt) {
        unsigned abase = smem_u32(As + (size_t)buf * A_ST);
        unsigned bbase = smem_u32(Bs + (size_t)buf * B_ST);
        #pragma unroll
        for (int p = 0; p < 4; p++) {       // A: 128 rows x 8 chunks of 16B
            int cid = p * 256 + tid;
            int r = cid >> 3, c = cid & 7;
            unsigned dst = abase + (unsigned)((r * LDS_H + c * 8) * 2);
            const __half* src = Abase + (size_t)r * K + kt * BK + c * 8;
            asm volatile("cp.async.cg.shared.global [%0], [%1], 16;\n"
                         :: "r"(dst), "l"(src));
        }
        #pragma unroll
        for (int p = 0; p < 4; p++) {       // B: 128 rows x 8 chunks of 16B
            int cid = p * 256 + tid;
            int r = cid >> 3, c = cid & 7;
            unsigned dst = bbase + (unsigned)((r * LDS_H + c * 8) * 2);
            const __half* src = Bbase + (size_t)r * K + kt * BK + c * 8;
            asm volatile("cp.async.cg.shared.global [%0], [%1], 16;\n"
                         :: "r"(dst), "l"(src));
        }
    };

    load_stage(0, 0);
    asm volatile("cp.async.commit_group;\n");
    load_stage(1, 1);
    asm volatile("cp.async.commit_group;\n");

    int buf = 0;
    for (int kt = 0; kt < KT; kt++) {
        asm volatile("cp.async.wait_group 1;\n");
        __syncthreads();

        if (kt + 2 < KT) {
            int nb = buf + 2; if (nb >= STAGES) nb -= STAGES;
            load_stage(nb, kt + 2);
        }
        asm volatile("cp.async.commit_group;\n");

        unsigned abuf = smem_u32(As + (size_t)buf * A_ST);
        unsigned bbuf = smem_u32(Bs + (size_t)buf * B_ST);

        #pragma unroll
        for (int ks = 0; ks < 4; ks++) {    // four k=16 slices per BK=64
            uint32_t af[4][4], bf[2][4];
            #pragma unroll
            for (int mi = 0; mi < 4; mi++) {
                unsigned addr = abuf + (unsigned)(((wm + mi * 16 + a_row_off) * LDS_H
                                                  + ks * 16 + a_khalf * 8) * 2);
                asm volatile("ldmatrix.sync.aligned.m8n8.x4.shared.b16 "
                             "{%0,%1,%2,%3}, [%4];"
                             : "=r"(af[mi][0]), "=r"(af[mi][1]),
                               "=r"(af[mi][2]), "=r"(af[mi][3]) : "r"(addr));
            }
            #pragma unroll
            for (int np = 0; np < 2; np++) {
                unsigned addr = bbuf + (unsigned)(((wn + np * 16 + b_row_off) * LDS_H
                                                  + ks * 16 + b_khalf * 8) * 2);
                asm volatile("ldmatrix.sync.aligned.m8n8.x4.shared.b16 "
                             "{%0,%1,%2,%3}, [%4];"
                             : "=r"(bf[np][0]), "=r"(bf[np][1]),
                               "=r"(bf[np][2]), "=r"(bf[np][3]) : "r"(addr));
            }
            #pragma unroll
            for (int mi = 0; mi < 4; mi++)
                #pragma unroll
                for (int np = 0; np < 2; np++) {
                    asm volatile(
                        "mma.sync.aligned.m16n8k16.row.col.f32.f16.f16.f32 "
                        "{%0,%1,%2,%3}, {%4,%5,%6,%7}, {%8,%9}, {%0,%1,%2,%3};\n"
                        : "+f"(acc[mi][2*np][0]), "+f"(acc[mi][2*np][1]),
                          "+f"(acc[mi][2*np][2]), "+f"(acc[mi][2*np][3])
                        : "r"(af[mi][0]), "r"(af[mi][1]), "r"(af[mi][2]), "r"(af[mi][3]),
                          "r"(bf[np][0]), "r"(bf[np][1]));
                    asm volatile(
                        "mma.sync.aligned.m16n8k16.row.col.f32.f16.f16.f32 "
                        "{%0,%1,%2,%3}, {%4,%5,%6,%7}, {%8,%9}, {%0,%1,%2,%3};\n"
                        : "+f"(acc[mi][2*np+1][0]), "+f"(acc[mi][2*np+1][1]),
                          "+f"(acc[mi][2*np+1][2]), "+f"(acc[mi][2*np+1][3])
                        : "r"(af[mi][0]), "r"(af[mi][1]), "r"(af[mi][2]), "r"(af[mi][3]),
                          "r"(bf[np][2]), "r"(bf[np][3]));
                }
        }
        if (++buf == STAGES) buf = 0;
    }

    // epilogue
    #pragma unroll
    for (int mi = 0; mi < 4; mi++) {
        int row0 = mtile * BM + wm + mi * 16 + g;
        #pragma unroll
        for (int ni = 0; ni < 4; ni++) {
            int col = ntile * BN + wn + ni * 8 + tg * 2;
            float2 v0 = make_float2(acc[mi][ni][0], acc[mi][ni][1]);
            float2 v1 = make_float2(acc[mi][ni][2], acc[mi][ni][3]);
            *reinterpret_cast<float2*>(&C[(size_t)row0 * N + col])       = v0;
            *reinterpret_cast<float2*>(&C[(size_t)(row0 + 8) * N + col]) = v1;
        }
    }
}

// ---------------------------------------------------------------------------
// Launcher
// ---------------------------------------------------------------------------
extern "C" void kernel_launch(void* const* d_in, const int* in_sizes, int n_in,
                              void* d_out, int out_size) {
    const float* x      = (const float*)d_in[0];
    const int*   wq     = (const int*)  d_in[1];
    const float* scales = (const float*)d_in[2];
    const float* la     = (const float*)d_in[3];
    const float* lb     = (const float*)d_in[4];
    float* out = (float*)d_out;

    int M = in_sizes[0] / IN_DIM;    // 8192

    __half *gw = nullptr, *gx = nullptr;
    cudaGetSymbolAddress((void**)&gw, g_w);
    cudaGetSymbolAddress((void**)&gx, g_x);

    // prep: X rounding + W' dequant/fold (one launch)
    int n8x    = (M * IN_DIM) / 8;
    int nblk_x = (n8x + 255) / 256;
    int n4w    = OUT_DIM * (IN_DIM / 4);
    int nblk_w = (n4w + 255) / 256;
    prep_kernel<<<nblk_x + nblk_w, 256>>>(x, gx, n8x, nblk_x,
                                          wq, scales, la, lb, gw);

    const int smem_bytes = STAGES * (A_ST + B_ST) * (int)sizeof(__half); // 110592
    cudaFuncSetAttribute(gemm_fp16_kernel,
                         cudaFuncAttributeMaxDynamicSharedMemorySize, smem_bytes);
    int grid = (M / BM) * (OUT_DIM / BN);   // 2048

    // PDL launch (fallback to plain launch if attribute rejected)
    cudaLaunchConfig_t cfg = {};
    cfg.gridDim  = dim3(grid, 1, 1);
    cfg.blockDim = dim3(256, 1, 1);
    cfg.dynamicSmemBytes = smem_bytes;
    cudaLaunchAttribute attrs[1];
    attrs[0].id = cudaLaunchAttributeProgrammaticStreamSerialization;
    attrs[0].val.programmaticStreamSerializationAllowed = 1;
    cfg.attrs = attrs;
    cfg.numAttrs = 1;
    cudaError_t e = cudaLaunchKernelEx(&cfg, gemm_fp16_kernel,
                                       (const __half*)gx, (const __half*)gw,
                                       out, M, OUT_DIM, IN_DIM);
    if (e != cudaSuccess) {
        gemm_fp16_kernel<<<grid, 256, smem_bytes>>>(gx, gw, out, M, OUT_DIM, IN_DIM);
    }
}